// round 6
// baseline (speedup 1.0000x reference)
#include <cuda_runtime.h>
#include <math.h>
#include <float.h>

#define BB 256
#define TT 200
#define EE 100
#define EP 112
#define HH 512
#define G4 2048
#define NCLS 5
#define VV 50000
#define MROWS (TT*BB)

// ---------------- static device scratch ----------------
__device__ float g_xe[(size_t)MROWS * EP];
__device__ float g_W0p[(size_t)G4 * EP];
__device__ float g_G[(size_t)MROWS * G4];
__device__ float g_h0s[(size_t)MROWS * HH];   // layer0 h archive (A for G1 GEMM)
__device__ float g_h1[4 * BB * HH];           // layer1 h ring buffer (4-deep)
__device__ float g_pooled[BB * HH];
__device__ int   g_last[BB];
__device__ unsigned g_bar[2][4];               // [layer][m-group] arrival counters

// ---------------- packed f32x2 helpers ----------------
__device__ __forceinline__ unsigned long long pk2(float lo, float hi) {
    unsigned long long r;
    asm("mov.b64 %0, {%1,%2};" : "=l"(r) : "f"(lo), "f"(hi));
    return r;
}
__device__ __forceinline__ void upk2(float& lo, float& hi, unsigned long long v) {
    asm("mov.b64 {%0,%1}, %2;" : "=f"(lo), "=f"(hi) : "l"(v));
}
__device__ __forceinline__ void fma2(unsigned long long& d, unsigned long long a, unsigned long long b) {
    asm("fma.rn.f32x2 %0, %1, %2, %0;" : "+l"(d) : "l"(a), "l"(b));
}
__device__ __forceinline__ void bar_arrive_release(unsigned* p) {
    unsigned dummy;
    asm volatile("atom.release.gpu.global.add.u32 %0, [%1], 1;"
                 : "=r"(dummy) : "l"(p) : "memory");
}
__device__ __forceinline__ unsigned bar_ld_acquire(const unsigned* p) {
    unsigned v;
    asm volatile("ld.acquire.gpu.global.u32 %0, [%1];" : "=r"(v) : "l"(p) : "memory");
    return v;
}
__device__ __forceinline__ float sigf(float x)   { return 1.0f / (1.0f + __expf(-x)); }
__device__ __forceinline__ float tanhf_(float x) { return 2.0f / (1.0f + __expf(-2.0f * x)) - 1.0f; }

// ---------------- prep kernels ----------------
__global__ void k_last(const int* __restrict__ X) {
    int b = threadIdx.x;
    if (b < BB) {
        int l = -1;
        for (int t = 0; t < TT; t++)
            if (X[b * TT + t] != VV) l = t;
        g_last[b] = l;
    }
}

__global__ void k_padw0(const float* __restrict__ W) {
    int idx = blockIdx.x * blockDim.x + threadIdx.x;
    if (idx < 8) ((unsigned*)g_bar)[idx] = 0u;      // reset barrier counters every call
    if (idx < G4 * EP) {
        int n = idx / EP, k = idx % EP;
        g_W0p[idx] = (k < EE) ? W[n * EE + k] : 0.0f;
    }
}

__global__ void k_gather(const int* __restrict__ X, const float* __restrict__ emb) {
    int row = blockIdx.x;
    int t = row / BB, b = row % BB;
    int tok = X[b * TT + t];
    const float* src = emb + (size_t)tok * EE;
    for (int e = threadIdx.x; e < EP; e += blockDim.x)
        g_xe[(size_t)row * EP + e] = (e < EE) ? src[e] : 0.0f;
}

// ---------------- input GEMM: C[M,4H] = A[M,K] @ W[4H,K]^T + bias ----------------
__global__ void __launch_bounds__(256) k_gemm(const float* __restrict__ Wihp,
                                              const float* __restrict__ bias,
                                              int which) {
    const float* A; const float* W; int K;
    if (which == 0) { A = g_xe;  W = g_W0p; K = EP; }
    else            { A = g_h0s; W = Wihp;  K = HH; }
    float* C = g_G;

    __shared__ float As[16][132];
    __shared__ float Bs[16][132];

    int m0 = blockIdx.y * 128, n0 = blockIdx.x * 128;
    int tx = threadIdx.x;
    int tn = tx & 15, tm = tx >> 4;

    unsigned long long acc[8][4];
#pragma unroll
    for (int i = 0; i < 8; i++)
#pragma unroll
        for (int j = 0; j < 4; j++) acc[i][j] = 0ull;

    int nt = K / 16;
    float4 va[2], vb[2];
#pragma unroll
    for (int i = 0; i < 2; i++) {
        int id = i * 256 + tx;
        int row = id >> 2, kq = (id & 3) * 4;
        va[i] = *(const float4*)(A + (size_t)(m0 + row) * K + kq);
        vb[i] = *(const float4*)(W + (size_t)(n0 + row) * K + kq);
    }

#pragma unroll 1
    for (int kt = 0; kt < nt; kt++) {
        float4 nva[2], nvb[2];
        if (kt + 1 < nt) {
            int k0n = (kt + 1) * 16;
#pragma unroll
            for (int i = 0; i < 2; i++) {
                int id = i * 256 + tx;
                int row = id >> 2, kq = (id & 3) * 4;
                nva[i] = *(const float4*)(A + (size_t)(m0 + row) * K + k0n + kq);
                nvb[i] = *(const float4*)(W + (size_t)(n0 + row) * K + k0n + kq);
            }
        }
#pragma unroll
        for (int i = 0; i < 2; i++) {
            int id = i * 256 + tx;
            int row = id >> 2, kq = (id & 3) * 4;
            As[kq + 0][row] = va[i].x; As[kq + 1][row] = va[i].y;
            As[kq + 2][row] = va[i].z; As[kq + 3][row] = va[i].w;
            Bs[kq + 0][row] = vb[i].x; Bs[kq + 1][row] = vb[i].y;
            Bs[kq + 2][row] = vb[i].z; Bs[kq + 3][row] = vb[i].w;
        }
        __syncthreads();
#pragma unroll
        for (int k = 0; k < 16; k++) {
            float4 a0 = *(const float4*)&As[k][tm * 4];
            float4 a1 = *(const float4*)&As[k][64 + tm * 4];
            unsigned long long pb[4];
            pb[0] = *(const unsigned long long*)&Bs[k][tn * 4];
            pb[1] = *(const unsigned long long*)&Bs[k][tn * 4 + 2];
            pb[2] = *(const unsigned long long*)&Bs[k][64 + tn * 4];
            pb[3] = *(const unsigned long long*)&Bs[k][64 + tn * 4 + 2];
            float am[8] = { a0.x, a0.y, a0.z, a0.w, a1.x, a1.y, a1.z, a1.w };
#pragma unroll
            for (int mi = 0; mi < 8; mi++) {
                unsigned long long pa = pk2(am[mi], am[mi]);
#pragma unroll
                for (int np = 0; np < 4; np++) fma2(acc[mi][np], pa, pb[np]);
            }
        }
        __syncthreads();
#pragma unroll
        for (int i = 0; i < 2; i++) { va[i] = nva[i]; vb[i] = nvb[i]; }
    }

    float4 bi0 = *(const float4*)(bias + n0 + tn * 4);
    float4 bi1 = *(const float4*)(bias + n0 + 64 + tn * 4);
#pragma unroll
    for (int mi = 0; mi < 8; mi++) {
        int row = m0 + ((mi < 4) ? (tm * 4 + mi) : (64 + tm * 4 + mi - 4));
        float4 o;
        upk2(o.x, o.y, acc[mi][0]); upk2(o.z, o.w, acc[mi][1]);
        o.x += bi0.x; o.y += bi0.y; o.z += bi0.z; o.w += bi0.w;
        *(float4*)(C + (size_t)row * G4 + n0 + tn * 4) = o;
        upk2(o.x, o.y, acc[mi][2]); upk2(o.z, o.w, acc[mi][3]);
        o.x += bi1.x; o.y += bi1.y; o.z += bi1.z; o.w += bi1.w;
        *(float4*)(C + (size_t)row * G4 + n0 + 64 + tn * 4) = o;
    }
}

// ---------------- persistent recurrence kernel ----------------
// grid (32 j-tiles, 4 m-tiles) = 128 CTAs, 256 threads.
// CTA tile: 64m x (4g x 16j) x 512k.  W slab resident in SMEM.
// Per-m-group barrier with FORMAL acquire/release atomics.
#define WS_STRIDE 68
#define RS_WS   (HH * WS_STRIDE)                // 34816 floats
#define RS_AS   (2 * 32 * 130)                  // double-buffered dup-A staging
#define RS_SMEM ((RS_WS + RS_AS) * 4)

template<int LAYER>
__global__ void __launch_bounds__(256) k_recur(const float* __restrict__ Whh) {
    extern __shared__ float sm[];
    float* Ws  = sm;                 // [512][68]
    float* As2 = sm + RS_WS;         // [2][32][130]

    int j0 = blockIdx.x * 16;
    int m0 = blockIdx.y * 64;
    unsigned* bar = &g_bar[LAYER][blockIdx.y];
    int tx = threadIdx.x;
    int tj = tx & 7, tm = tx >> 3;   // tj 0..7, tm 0..31

    // ---- stage W slab once ----
    {
        int c = tx >> 2;
        int blk = c >> 5, tjj = (c >> 2) & 7, rem = c & 3;
        int g = 2 * blk + (rem >> 1);
        int jj = j0 + 2 * tjj + (rem & 1);
        int kb = (tx & 3) * 128;
        const float* wr = Whh + (size_t)(g * HH + jj) * HH + kb;
#pragma unroll 4
        for (int k = 0; k < 128; k += 4) {
            float4 v = *(const float4*)(wr + k);
            int kk = kb + k;
            Ws[(kk + 0) * WS_STRIDE + c] = v.x;
            Ws[(kk + 1) * WS_STRIDE + c] = v.y;
            Ws[(kk + 2) * WS_STRIDE + c] = v.z;
            Ws[(kk + 3) * WS_STRIDE + c] = v.w;
        }
    }
    __syncthreads();

    float2 cst[2] = { {0.f, 0.f}, {0.f, 0.f} };
    float2 pool[2];
    int lastv[2];
    if (LAYER == 1) {
        pool[0] = make_float2(-FLT_MAX, -FLT_MAX);
        pool[1] = make_float2(-FLT_MAX, -FLT_MAX);
        lastv[0] = g_last[m0 + 2 * tm];
        lastv[1] = g_last[m0 + 2 * tm + 1];
    }

    // staging ids (proven R3 mapping)
    int sr0 = tx >> 3, sq0 = (tx & 7) * 4;
    int sr1 = 32 + (tx >> 3);

    // prefetch gate inputs for t=0
    float2 gv[2][4];
    {
        const float* Gt = g_G;
#pragma unroll
        for (int mi = 0; mi < 2; mi++) {
            const float* gr = Gt + (size_t)(m0 + 2 * tm + mi) * G4 + j0 + 2 * tj;
#pragma unroll
            for (int g = 0; g < 4; g++) gv[mi][g] = __ldcg((const float2*)(gr + g * 512));
        }
    }

    for (int t = 0; t < TT; t++) {
        unsigned long long acc[2][4];
#pragma unroll
        for (int mi = 0; mi < 2; mi++)
#pragma unroll
            for (int g = 0; g < 4; g++) acc[mi][g] = 0ull;

        if (t > 0) {
            const float* hp = (LAYER == 0)
                ? g_h0s + (size_t)(t - 1) * BB * HH
                : g_h1 + (size_t)((t - 1) & 3) * BB * HH;
            float4 pA = __ldcg((const float4*)(hp + (size_t)(m0 + sr0) * HH + sq0));
            float4 pB = __ldcg((const float4*)(hp + (size_t)(m0 + sr1) * HH + sq0));
#pragma unroll 1
            for (int kt = 0; kt < 16; kt++) {
                float4 nA, nB;
                if (kt + 1 < 16) {
                    int k0n = (kt + 1) * 32;
                    nA = __ldcg((const float4*)(hp + (size_t)(m0 + sr0) * HH + k0n + sq0));
                    nB = __ldcg((const float4*)(hp + (size_t)(m0 + sr1) * HH + k0n + sq0));
                }
                float* Ab = As2 + (kt & 1) * (32 * 130);
                *(unsigned long long*)&Ab[(sq0 + 0) * 130 + 2 * sr0] = pk2(pA.x, pA.x);
                *(unsigned long long*)&Ab[(sq0 + 1) * 130 + 2 * sr0] = pk2(pA.y, pA.y);
                *(unsigned long long*)&Ab[(sq0 + 2) * 130 + 2 * sr0] = pk2(pA.z, pA.z);
                *(unsigned long long*)&Ab[(sq0 + 3) * 130 + 2 * sr0] = pk2(pA.w, pA.w);
                *(unsigned long long*)&Ab[(sq0 + 0) * 130 + 2 * sr1] = pk2(pB.x, pB.x);
                *(unsigned long long*)&Ab[(sq0 + 1) * 130 + 2 * sr1] = pk2(pB.y, pB.y);
                *(unsigned long long*)&Ab[(sq0 + 2) * 130 + 2 * sr1] = pk2(pB.z, pB.z);
                *(unsigned long long*)&Ab[(sq0 + 3) * 130 + 2 * sr1] = pk2(pB.w, pB.w);
                __syncthreads();
                const float* WsK = Ws + (size_t)kt * 32 * WS_STRIDE;
#pragma unroll
                for (int k = 0; k < 32; k++) {
                    unsigned long long a0 = *(const unsigned long long*)&Ab[k * 130 + 4 * tm];
                    unsigned long long a1 = *(const unsigned long long*)&Ab[k * 130 + 4 * tm + 2];
                    ulonglong2 b01 = *(const ulonglong2*)&WsK[k * WS_STRIDE + tj * 4];
                    ulonglong2 b23 = *(const ulonglong2*)&WsK[k * WS_STRIDE + 32 + tj * 4];
                    fma2(acc[0][0], a0, b01.x); fma2(acc[0][1], a0, b01.y);
                    fma2(acc[0][2], a0, b23.x); fma2(acc[0][3], a0, b23.y);
                    fma2(acc[1][0], a1, b01.x); fma2(acc[1][1], a1, b01.y);
                    fma2(acc[1][2], a1, b23.x); fma2(acc[1][3], a1, b23.y);
                }
                pA = nA; pB = nB;
            }
        }

        // ---- epilogue ----
        float* hout = (LAYER == 0)
            ? g_h0s + (size_t)t * BB * HH
            : g_h1 + (size_t)(t & 3) * BB * HH;
#pragma unroll
        for (int mi = 0; mi < 2; mi++) {
            float i0, i1, f0, f1, gg0, gg1, o0, o1;
            upk2(i0, i1, acc[mi][0]);
            upk2(f0, f1, acc[mi][1]);
            upk2(gg0, gg1, acc[mi][2]);
            upk2(o0, o1, acc[mi][3]);
            i0 += gv[mi][0].x; i1 += gv[mi][0].y;
            f0 += gv[mi][1].x; f1 += gv[mi][1].y;
            gg0 += gv[mi][2].x; gg1 += gv[mi][2].y;
            o0 += gv[mi][3].x; o1 += gv[mi][3].y;

            float c0 = sigf(f0) * cst[mi].x + sigf(i0) * tanhf_(gg0);
            float c1 = sigf(f1) * cst[mi].y + sigf(i1) * tanhf_(gg1);
            cst[mi].x = c0; cst[mi].y = c1;
            float h0v = sigf(o0) * tanhf_(c0);
            float h1v = sigf(o1) * tanhf_(c1);

            int m = m0 + 2 * tm + mi;
            __stcg((float2*)(hout + (size_t)m * HH + j0 + 2 * tj), make_float2(h0v, h1v));

            if (LAYER == 1 && t <= lastv[mi]) {
                pool[mi].x = fmaxf(pool[mi].x, h0v);
                pool[mi].y = fmaxf(pool[mi].y, h1v);
            }
        }

        // ---- inter-step barrier: per-m-group, release-arrive + acquire-poll ----
        if (t != TT - 1) {
            __threadfence();                    // release side: order this thread's stores
            __syncthreads();
            if (tx == 0) bar_arrive_release(bar);
            // overlap: prefetch next step's gates (read-only data) while barrier settles
            {
                const float* Gt = g_G + (size_t)(t + 1) * BB * G4;
#pragma unroll
                for (int mi = 0; mi < 2; mi++) {
                    const float* gr = Gt + (size_t)(m0 + 2 * tm + mi) * G4 + j0 + 2 * tj;
#pragma unroll
                    for (int g = 0; g < 4; g++) gv[mi][g] = __ldcg((const float2*)(gr + g * 512));
                }
            }
            if (tx == 0) {
                unsigned target = 32u * (unsigned)(t + 1);
                while (bar_ld_acquire(bar) < target) { }
            }
            __syncthreads();
            __threadfence();                    // acquire side for all reader threads
        }
    }

    if (LAYER == 1) {
#pragma unroll
        for (int mi = 0; mi < 2; mi++) {
            int m = m0 + 2 * tm + mi;
            *(float2*)&g_pooled[m * HH + j0 + 2 * tj] = pool[mi];
        }
    }
}

// ---------------- final projection ----------------
__global__ void k_logits(const float* __restrict__ Wout, const float* __restrict__ bout,
                         float* __restrict__ out) {
    int b = blockIdx.x;
    int tx = threadIdx.x;
    float p[NCLS] = {0, 0, 0, 0, 0};
    for (int k = tx; k < HH; k += 128) {
        float v = g_pooled[b * HH + k];
#pragma unroll
        for (int c = 0; c < NCLS; c++) p[c] += v * Wout[c * HH + k];
    }
#pragma unroll
    for (int off = 16; off; off >>= 1)
#pragma unroll
        for (int c = 0; c < NCLS; c++) p[c] += __shfl_down_sync(0xffffffffu, p[c], off);
    __shared__ float red[4][NCLS];
    if ((tx & 31) == 0)
#pragma unroll
        for (int c = 0; c < NCLS; c++) red[tx >> 5][c] = p[c];
    __syncthreads();
    if (tx == 0) {
#pragma unroll
        for (int c = 0; c < NCLS; c++)
            out[b * NCLS + c] = red[0][c] + red[1][c] + red[2][c] + red[3][c] + bout[c];
    }
}

// ---------------- launch ----------------
extern "C" void kernel_launch(void* const* d_in, const int* in_sizes, int n_in,
                              void* d_out, int out_size) {
    (void)in_sizes; (void)n_in; (void)out_size;
    const int*   X      = (const int*)d_in[0];
    const float* emb    = (const float*)d_in[1];
    const float* W_ih0  = (const float*)d_in[2];
    const float* W_hh0  = (const float*)d_in[3];
    const float* b0     = (const float*)d_in[4];
    const float* W_ih1  = (const float*)d_in[5];
    const float* W_hh1  = (const float*)d_in[6];
    const float* b1     = (const float*)d_in[7];
    const float* W_out  = (const float*)d_in[8];
    const float* b_out  = (const float*)d_in[9];
    float* out = (float*)d_out;

    cudaFuncSetAttribute(k_recur<0>, cudaFuncAttributeMaxDynamicSharedMemorySize, RS_SMEM);
    cudaFuncSetAttribute(k_recur<1>, cudaFuncAttributeMaxDynamicSharedMemorySize, RS_SMEM);

    // order keeps k_recur<0> in the ncu capture slot
    k_padw0<<<(G4 * EP + 255) / 256, 256>>>(W_ih0);          // 1 (also zeroes barriers)
    k_gather<<<MROWS, 128>>>(X, emb);                        // 2
    k_gemm<<<dim3(16, 400), 256>>>(nullptr, b0, 0);          // 3
    k_recur<0><<<dim3(32, 4), 256, RS_SMEM>>>(W_hh0);        // 4  <- capture target
    k_last<<<1, 256>>>(X);                                   // 5
    k_gemm<<<dim3(16, 400), 256>>>(W_ih1, b1, 1);            // 6
    k_recur<1><<<dim3(32, 4), 256, RS_SMEM>>>(W_hh1);        // 7
    k_logits<<<BB, 128>>>(W_out, b_out, out);                // 8
}